// round 5
// baseline (speedup 1.0000x reference)
#include <cuda_runtime.h>

// Problem constants
#define B_TOT 2048
#define T_LEN 128
#define DIN   64
#define UDIM  128
#define NG    512   // 4*U
#define KTOT  192   // DIN + U
#define SLOTS 16    // batch slots per CTA (padded)
#define NTH   512
#define XH_S  20    // padded row stride for [x|h] tile (floats)
#define GS_S  20    // padded row stride for gate staging (floats)
#define KUF   4     // weight prefetch block
#define GRIDX 148   // CTAs per path: perfect 1-wave at occupancy 2 (148 SMs)
#define NFULL 124   // first 124 CTAs take 14 rows, rest take 13 (124*14+24*13=2048)

#define SMEM_XH_FLOATS (KTOT * XH_S)             // 3840
#define SMEM_GS_FLOATS (NG * GS_S)               // 10240
#define SMEM_TOTAL_BYTES ((SMEM_XH_FLOATS + SMEM_GS_FLOATS) * 4)  // 56320

// Pre-transposed fused weights: g_Wt[k][n], k in [0,192): k<64 -> W_ih, else W_hh
__device__ float g_Wt[KTOT * NG];
__device__ float g_bias[NG];

__global__ void prep_kernel(const float* __restrict__ W_ih, const float* __restrict__ W_hh,
                            const float* __restrict__ b_ih, const float* __restrict__ b_hh) {
    int k = blockIdx.x;
    int n = threadIdx.x;
    g_Wt[k * NG + n] = (k < DIN) ? W_ih[n * DIN + k] : W_hh[n * UDIM + (k - DIN)];
    if (k == 0) g_bias[n] = b_ih[n] + b_hh[n];
}

__device__ __forceinline__ float fsig(float x) {
    return 1.0f / (1.0f + __expf(-x));
}
__device__ __forceinline__ float ftanh(float x) {
    float a = fabsf(x);
    float e = __expf(2.0f * a);
    float r = 1.0f - 2.0f / (1.0f + e);
    return copysignf(r, x);
}

// packed fp32x2 FMA (sm_100a): d = a*b + d  (same fp32 RN rounding as FFMA)
#define FFMA2(d, a, b) \
    asm("fma.rn.f32x2 %0, %1, %2, %0;" : "+l"(d) : "l"(a), "l"(b))

__device__ __forceinline__ unsigned long long splat2(float w) {
    unsigned long long r;
    asm("mov.b64 %0, {%1, %1};" : "=l"(r) : "f"(w));
    return r;
}
__device__ __forceinline__ void unpack2(unsigned long long p, float& lo, float& hi) {
    asm("mov.b64 {%0, %1}, %2;" : "=f"(lo), "=f"(hi) : "l"(p));
}

__global__ void __launch_bounds__(NTH, 2)
lstm_kernel(const float* __restrict__ x_st, const float* __restrict__ x_sc,
            const float* __restrict__ bn_gamma, const float* __restrict__ bn_beta,
            const float* __restrict__ bn_mean, const float* __restrict__ bn_var,
            float* __restrict__ out) {
    // dynamic smem:
    //   sm_xh: [192][XH_S]  rows 0..63 = x_t (transposed, [k][b]), rows 64..191 = h ([u][b])
    //   sm_gs: [512][GS_S]  activated gates, [n][b]
    extern __shared__ float smem[];
    float* sm_xh = smem;
    float* sm_gs = smem + SMEM_XH_FLOATS;

    const int path = blockIdx.y;             // 0 = SNN (st), 1 = ANN (sc)
    const int bx   = blockIdx.x;
    // uneven tiling: first NFULL CTAs own 14 rows, the rest 13 (sum = 2048)
    const int start = (bx < NFULL) ? 14 * bx : 14 * NFULL + 13 * (bx - NFULL);
    const int bt    = (bx < NFULL) ? 14 : 13;

    const float* __restrict__ xin = (path == 0) ? x_st : x_sc;

    const int n    = threadIdx.x;            // gate column this thread computes
    const int u    = n & (UDIM - 1);         // state unit this thread owns
    const int gate = n >> 7;                 // 0:i 1:f 2:g 3:o
    const int b0   = gate * 4;               // this thread owns batch slots b0..b0+3 of state

    // x staging: thread handles elements n and n+512 of the 1024-elem x tile.
    // Padding slots (b >= bt) duplicate the last real row — computed, never stored.
    const int xb0 = n >> 6, xk0 = n & 63;          // slot for element n
    const int xb1 = (n + NTH) >> 6;                // slot for element n+512 (same k)
    const int rb0 = start + ((xb0 < bt) ? xb0 : (bt - 1));
    const int rb1 = start + ((xb1 < bt) ? xb1 : (bt - 1));
    const float* __restrict__ xp0 = xin + (size_t)rb0 * T_LEN * DIN + xk0;
    const float* __restrict__ xp1 = xin + (size_t)rb1 * T_LEN * DIN + xk0;

    // zero the whole [x|h] tile (h starts at 0, pads stay 0)
    for (int i = n; i < SMEM_XH_FLOATS; i += NTH) sm_xh[i] = 0.0f;

    float c[4], m[4], s[4];
#pragma unroll
    for (int j = 0; j < 4; j++) { c[j] = 0.0f; m[j] = 0.0f; s[j] = 0.0f; }

    const float bias = g_bias[n];
    const unsigned long long biasp = splat2(bias);
    const float* __restrict__ Wp = g_Wt + n;

    // preload x_0 and stage it (pre-barrier, so no race)
    float rx0 = xp0[0];
    float rx1 = xp1[0];
    sm_xh[xk0 * XH_S + xb0] = rx0;
    sm_xh[xk0 * XH_S + xb1] = rx1;

    for (int t = 0; t < T_LEN; t++) {
        __syncthreads();   // (A) x_t and h_t visible to everyone

        // issue next step's x loads early; consumed after barrier (B)
        if (t + 1 < T_LEN) {
            rx0 = xp0[(size_t)(t + 1) * DIN];
            rx1 = xp1[(size_t)(t + 1) * DIN];
        }

        // ---- gates[b][n] = sum_k xh[k][b] * Wt[k][n] + bias (packed f32x2) ----
        unsigned long long acc[8];
#pragma unroll
        for (int j = 0; j < 8; j++) acc[j] = biasp;

        float w[KUF], wn[KUF];
#pragma unroll
        for (int i = 0; i < KUF; i++) w[i] = __ldg(Wp + i * NG);

        for (int kb = 0; kb < KTOT; kb += KUF) {
            if (kb + KUF < KTOT) {
#pragma unroll
                for (int i = 0; i < KUF; i++) wn[i] = __ldg(Wp + (kb + KUF + i) * NG);
            }
#pragma unroll
            for (int i = 0; i < KUF; i++) {
                unsigned long long wp = splat2(w[i]);
                const ulonglong2* xr = (const ulonglong2*)(sm_xh + (kb + i) * XH_S);
                ulonglong2 p0 = xr[0];   // batch pairs (0,1),(2,3)
                ulonglong2 p1 = xr[1];   // (4,5),(6,7)
                ulonglong2 p2 = xr[2];   // (8,9),(10,11)
                ulonglong2 p3 = xr[3];   // (12,13),(14,15)
                FFMA2(acc[0], p0.x, wp);
                FFMA2(acc[1], p0.y, wp);
                FFMA2(acc[2], p1.x, wp);
                FFMA2(acc[3], p1.y, wp);
                FFMA2(acc[4], p2.x, wp);
                FFMA2(acc[5], p2.y, wp);
                FFMA2(acc[6], p3.x, wp);
                FFMA2(acc[7], p3.y, wp);
            }
#pragma unroll
            for (int i = 0; i < KUF; i++) w[i] = wn[i];
        }

        // ---- activations, stage to smem ----
        float va[16];
#pragma unroll
        for (int j = 0; j < 8; j++) unpack2(acc[j], va[2 * j], va[2 * j + 1]);
        if (gate == 2) {
#pragma unroll
            for (int j = 0; j < 16; j++) va[j] = ftanh(va[j]);
        } else {
#pragma unroll
            for (int j = 0; j < 16; j++) va[j] = fsig(va[j]);
        }
        float4* gw = (float4*)(sm_gs + n * GS_S);
        gw[0] = make_float4(va[0],  va[1],  va[2],  va[3]);
        gw[1] = make_float4(va[4],  va[5],  va[6],  va[7]);
        gw[2] = make_float4(va[8],  va[9],  va[10], va[11]);
        gw[3] = make_float4(va[12], va[13], va[14], va[15]);
        __syncthreads();   // (B) all gates visible; all gemm reads of sm_xh done

        // ---- stage next x_t (safe now: gemm reads finished) ----
        if (t + 1 < T_LEN) {
            sm_xh[xk0 * XH_S + xb0] = rx0;
            sm_xh[xk0 * XH_S + xb1] = rx1;
        }

        // ---- state update: thread owns (u, slots b0..b0+3) ----
        float4 iv = *(const float4*)(sm_gs + (0 * UDIM + u) * GS_S + b0);
        float4 fv = *(const float4*)(sm_gs + (1 * UDIM + u) * GS_S + b0);
        float4 gv = *(const float4*)(sm_gs + (2 * UDIM + u) * GS_S + b0);
        float4 ov = *(const float4*)(sm_gs + (3 * UDIM + u) * GS_S + b0);
        float ia[4] = {iv.x, iv.y, iv.z, iv.w};
        float fa[4] = {fv.x, fv.y, fv.z, fv.w};
        float ga[4] = {gv.x, gv.y, gv.z, gv.w};
        float oa[4] = {ov.x, ov.y, ov.z, ov.w};
        float hv[4];
        if (path) {        // ANN: h = o * tanh(c)
#pragma unroll
            for (int j = 0; j < 4; j++) {
                c[j] = fa[j] * c[j] + ia[j] * ga[j];
                hv[j] = oa[j] * ftanh(c[j]);
                s[j] += hv[j];
            }
        } else {           // SNN: integrate-and-fire, spikes feed back as h
#pragma unroll
            for (int j = 0; j < 4; j++) {
                c[j] = fa[j] * c[j] + ia[j] * ga[j];
                m[j] += oa[j] * ftanh(c[j]);
                float spk = (m[j] >= 1.0f) ? 1.0f : 0.0f;
                m[j] -= spk;
                hv[j] = spk;
                s[j] += spk;
            }
        }
        float* hw = sm_xh + (DIN + u) * XH_S + b0;
        hw[0] = hv[0]; hw[1] = hv[1]; hw[2] = hv[2]; hw[3] = hv[3];
        // next iteration's barrier (A) orders these writes before the next gemm
    }

    // ---- epilogue: temporal mean + BatchNorm (eval mode); skip padding slots ----
    float scale = bn_gamma[u] * rsqrtf(bn_var[u] + 1e-5f);
    float shift = bn_beta[u] - bn_mean[u] * scale;
    const float inv = 1.0f / (float)T_LEN;
#pragma unroll
    for (int j = 0; j < 4; j++) {
        if (b0 + j < bt) {
            size_t ob = ((size_t)path * B_TOT + start + b0 + j) * UDIM + u;
            out[ob] = s[j] * inv * scale + shift;
        }
    }
}

extern "C" void kernel_launch(void* const* d_in, const int* in_sizes, int n_in,
                              void* d_out, int out_size) {
    const float* x_st  = (const float*)d_in[0];
    const float* x_sc  = (const float*)d_in[1];
    const float* W_ih  = (const float*)d_in[2];
    const float* W_hh  = (const float*)d_in[3];
    const float* b_ih  = (const float*)d_in[4];
    const float* b_hh  = (const float*)d_in[5];
    const float* gamma = (const float*)d_in[6];
    const float* beta  = (const float*)d_in[7];
    const float* mean  = (const float*)d_in[8];
    const float* var   = (const float*)d_in[9];

    // raise dynamic smem limit (idempotent; not a stream op, graph-capture safe)
    cudaFuncSetAttribute(lstm_kernel, cudaFuncAttributeMaxDynamicSharedMemorySize,
                         SMEM_TOTAL_BYTES);

    prep_kernel<<<KTOT, NG>>>(W_ih, W_hh, b_ih, b_hh);

    dim3 grid(GRIDX, 2);
    lstm_kernel<<<grid, NTH, SMEM_TOTAL_BYTES>>>(x_st, x_sc, gamma, beta, mean, var,
                                                 (float*)d_out);
}

// round 6
// speedup vs baseline: 1.3492x; 1.3492x over previous
#include <cuda_runtime.h>

// Problem constants
#define B_TOT 2048
#define T_LEN 128
#define DIN   64
#define UDIM  128
#define NG    512   // 4*U
#define KTOT  192   // DIN + U
#define BT    16    // batch rows per CTA
#define NTH   256   // threads: each owns TWO adjacent gate columns
#define XH_S  20    // padded row stride for [x|h] tile (floats)
#define GS_S  20    // padded row stride for gate staging (floats)
#define KUF   4     // weight prefetch block

#define SMEM_XH_FLOATS (KTOT * XH_S)             // 3840
#define SMEM_GS_FLOATS (NG * GS_S)               // 10240
#define SMEM_TOTAL_BYTES ((SMEM_XH_FLOATS + SMEM_GS_FLOATS) * 4)  // 56320

// Pre-transposed fused weights: g_Wt[k][n], k in [0,192): k<64 -> W_ih, else W_hh
__device__ float g_Wt[KTOT * NG];
__device__ float g_bias[NG];

__global__ void prep_kernel(const float* __restrict__ W_ih, const float* __restrict__ W_hh,
                            const float* __restrict__ b_ih, const float* __restrict__ b_hh) {
    int k = blockIdx.x;
    int n = threadIdx.x;
    g_Wt[k * NG + n] = (k < DIN) ? W_ih[n * DIN + k] : W_hh[n * UDIM + (k - DIN)];
    if (k == 0) g_bias[n] = b_ih[n] + b_hh[n];
}

__device__ __forceinline__ float fsig(float x) {
    return 1.0f / (1.0f + __expf(-x));
}
__device__ __forceinline__ float ftanh(float x) {
    float a = fabsf(x);
    float e = __expf(2.0f * a);
    float r = 1.0f - 2.0f / (1.0f + e);
    return copysignf(r, x);
}

// packed fp32x2 FMA (sm_100a): d = a*b + d  (same fp32 RN rounding as FFMA)
#define FFMA2(d, a, b) \
    asm("fma.rn.f32x2 %0, %1, %2, %0;" : "+l"(d) : "l"(a), "l"(b))

__device__ __forceinline__ unsigned long long splat2(float w) {
    unsigned long long r;
    asm("mov.b64 %0, {%1, %1};" : "=l"(r) : "f"(w));
    return r;
}
__device__ __forceinline__ void unpack2(unsigned long long p, float& lo, float& hi) {
    asm("mov.b64 {%0, %1}, %2;" : "=f"(lo), "=f"(hi) : "l"(p));
}

__global__ void __launch_bounds__(NTH, 2)
lstm_kernel(const float* __restrict__ x_st, const float* __restrict__ x_sc,
            const float* __restrict__ bn_gamma, const float* __restrict__ bn_beta,
            const float* __restrict__ bn_mean, const float* __restrict__ bn_var,
            float* __restrict__ out) {
    // dynamic smem:
    //   sm_xh: [192][XH_S]  rows 0..63 = x_t (transposed, [k][b]), rows 64..191 = h ([u][b])
    //   sm_gs: [512][GS_S]  activated gates, [n][b]
    extern __shared__ float smem[];
    float* sm_xh = smem;
    float* sm_gs = smem + SMEM_XH_FLOATS;

    const int path  = blockIdx.y;            // 0 = SNN (st), 1 = ANN (sc)
    const int bbase = blockIdx.x * BT;
    const float* __restrict__ xin = (path == 0) ? x_st : x_sc;
    const float* __restrict__ xrow = xin + (size_t)bbase * T_LEN * DIN;

    const int i    = threadIdx.x;            // owns gate columns n0=2i, n0+1
    const int n0   = 2 * i;
    const int gate = n0 >> 7;                // both columns share the gate (0:i 1:f 2:g 3:o)
    // state-update mapping: thread owns (u, 8 batch rows)
    const int u    = i & (UDIM - 1);
    const int jb   = i >> 7;                 // 0 or 1
    const int sb0  = jb * 8;                 // batch rows sb0..sb0+7

    // x staging: 1024 elements, 4 per thread (elements i, i+256, i+512, i+768)
    int xb[4], xk[4];
#pragma unroll
    for (int r = 0; r < 4; r++) { int e = i + r * NTH; xb[r] = e >> 6; xk[r] = e & 63; }

    // zero the whole [x|h] tile (h starts at 0, pads stay 0)
    for (int idx = i; idx < SMEM_XH_FLOATS; idx += NTH) sm_xh[idx] = 0.0f;

    float c[8], m[8], s[8];
#pragma unroll
    for (int j = 0; j < 8; j++) { c[j] = 0.0f; m[j] = 0.0f; s[j] = 0.0f; }

    const unsigned long long biasp0 = splat2(g_bias[n0]);
    const unsigned long long biasp1 = splat2(g_bias[n0 + 1]);
    const float2* __restrict__ Wp = (const float2*)(g_Wt + n0);  // stride NG/2 float2 per k

    // preload x_0 and stage it (pre-barrier, so no race)
    float rx[4];
#pragma unroll
    for (int r = 0; r < 4; r++) rx[r] = xrow[((size_t)xb[r] * T_LEN + 0) * DIN + xk[r]];
#pragma unroll
    for (int r = 0; r < 4; r++) sm_xh[xk[r] * XH_S + xb[r]] = rx[r];

    for (int t = 0; t < T_LEN; t++) {
        __syncthreads();   // (A) x_t and h_t visible to everyone

        // issue next step's x loads early; consumed after barrier (B)
        if (t + 1 < T_LEN) {
#pragma unroll
            for (int r = 0; r < 4; r++)
                rx[r] = xrow[((size_t)xb[r] * T_LEN + (t + 1)) * DIN + xk[r]];
        }

        // ---- gates[b][n] = sum_k xh[k][b] * Wt[k][n] + bias; 2 n-columns per thread ----
        unsigned long long a0[8], a1[8];
#pragma unroll
        for (int j = 0; j < 8; j++) { a0[j] = biasp0; a1[j] = biasp1; }

        float2 w[KUF], wn[KUF];
#pragma unroll
        for (int q = 0; q < KUF; q++) w[q] = __ldg(Wp + q * (NG / 2));

        for (int kb = 0; kb < KTOT; kb += KUF) {
            if (kb + KUF < KTOT) {
#pragma unroll
                for (int q = 0; q < KUF; q++) wn[q] = __ldg(Wp + (kb + KUF + q) * (NG / 2));
            }
#pragma unroll
            for (int q = 0; q < KUF; q++) {
                unsigned long long w0 = splat2(w[q].x);
                unsigned long long w1 = splat2(w[q].y);
                const ulonglong2* xr = (const ulonglong2*)(sm_xh + (kb + q) * XH_S);
                ulonglong2 p0 = xr[0];   // batch pairs (0,1),(2,3)
                ulonglong2 p1 = xr[1];   // (4,5),(6,7)
                ulonglong2 p2 = xr[2];   // (8,9),(10,11)
                ulonglong2 p3 = xr[3];   // (12,13),(14,15)
                FFMA2(a0[0], p0.x, w0);  FFMA2(a1[0], p0.x, w1);
                FFMA2(a0[1], p0.y, w0);  FFMA2(a1[1], p0.y, w1);
                FFMA2(a0[2], p1.x, w0);  FFMA2(a1[2], p1.x, w1);
                FFMA2(a0[3], p1.y, w0);  FFMA2(a1[3], p1.y, w1);
                FFMA2(a0[4], p2.x, w0);  FFMA2(a1[4], p2.x, w1);
                FFMA2(a0[5], p2.y, w0);  FFMA2(a1[5], p2.y, w1);
                FFMA2(a0[6], p3.x, w0);  FFMA2(a1[6], p3.x, w1);
                FFMA2(a0[7], p3.y, w0);  FFMA2(a1[7], p3.y, w1);
            }
#pragma unroll
            for (int q = 0; q < KUF; q++) w[q] = wn[q];
        }

        // ---- activations, stage to smem ----
        float v0[16], v1[16];
#pragma unroll
        for (int j = 0; j < 8; j++) {
            unpack2(a0[j], v0[2 * j], v0[2 * j + 1]);
            unpack2(a1[j], v1[2 * j], v1[2 * j + 1]);
        }
        if (gate == 2) {
#pragma unroll
            for (int j = 0; j < 16; j++) { v0[j] = ftanh(v0[j]); v1[j] = ftanh(v1[j]); }
        } else {
#pragma unroll
            for (int j = 0; j < 16; j++) { v0[j] = fsig(v0[j]); v1[j] = fsig(v1[j]); }
        }
        {
            float4* g0 = (float4*)(sm_gs + n0 * GS_S);
            g0[0] = make_float4(v0[0],  v0[1],  v0[2],  v0[3]);
            g0[1] = make_float4(v0[4],  v0[5],  v0[6],  v0[7]);
            g0[2] = make_float4(v0[8],  v0[9],  v0[10], v0[11]);
            g0[3] = make_float4(v0[12], v0[13], v0[14], v0[15]);
            float4* g1 = (float4*)(sm_gs + (n0 + 1) * GS_S);
            g1[0] = make_float4(v1[0],  v1[1],  v1[2],  v1[3]);
            g1[1] = make_float4(v1[4],  v1[5],  v1[6],  v1[7]);
            g1[2] = make_float4(v1[8],  v1[9],  v1[10], v1[11]);
            g1[3] = make_float4(v1[12], v1[13], v1[14], v1[15]);
        }
        __syncthreads();   // (B) all gates visible; all gemm reads of sm_xh done

        // ---- stage next x_t (safe now: gemm reads finished) ----
        if (t + 1 < T_LEN) {
#pragma unroll
            for (int r = 0; r < 4; r++) sm_xh[xk[r] * XH_S + xb[r]] = rx[r];
        }

        // ---- state update: thread owns (u, batch rows sb0..sb0+7) ----
        float ia[8], fa[8], ga[8], oa[8];
        {
            const float* gi = sm_gs + (0 * UDIM + u) * GS_S + sb0;
            const float* gf = sm_gs + (1 * UDIM + u) * GS_S + sb0;
            const float* gg = sm_gs + (2 * UDIM + u) * GS_S + sb0;
            const float* go = sm_gs + (3 * UDIM + u) * GS_S + sb0;
            float4 t0, t1;
            t0 = ((const float4*)gi)[0]; t1 = ((const float4*)gi)[1];
            ia[0]=t0.x; ia[1]=t0.y; ia[2]=t0.z; ia[3]=t0.w; ia[4]=t1.x; ia[5]=t1.y; ia[6]=t1.z; ia[7]=t1.w;
            t0 = ((const float4*)gf)[0]; t1 = ((const float4*)gf)[1];
            fa[0]=t0.x; fa[1]=t0.y; fa[2]=t0.z; fa[3]=t0.w; fa[4]=t1.x; fa[5]=t1.y; fa[6]=t1.z; fa[7]=t1.w;
            t0 = ((const float4*)gg)[0]; t1 = ((const float4*)gg)[1];
            ga[0]=t0.x; ga[1]=t0.y; ga[2]=t0.z; ga[3]=t0.w; ga[4]=t1.x; ga[5]=t1.y; ga[6]=t1.z; ga[7]=t1.w;
            t0 = ((const float4*)go)[0]; t1 = ((const float4*)go)[1];
            oa[0]=t0.x; oa[1]=t0.y; oa[2]=t0.z; oa[3]=t0.w; oa[4]=t1.x; oa[5]=t1.y; oa[6]=t1.z; oa[7]=t1.w;
        }
        float hv[8];
        if (path) {        // ANN: h = o * tanh(c)
#pragma unroll
            for (int j = 0; j < 8; j++) {
                c[j] = fa[j] * c[j] + ia[j] * ga[j];
                hv[j] = oa[j] * ftanh(c[j]);
                s[j] += hv[j];
            }
        } else {           // SNN: integrate-and-fire, spikes feed back as h
#pragma unroll
            for (int j = 0; j < 8; j++) {
                c[j] = fa[j] * c[j] + ia[j] * ga[j];
                m[j] += oa[j] * ftanh(c[j]);
                float spk = (m[j] >= 1.0f) ? 1.0f : 0.0f;
                m[j] -= spk;
                hv[j] = spk;
                s[j] += spk;
            }
        }
        {
            float4* hw = (float4*)(sm_xh + (DIN + u) * XH_S + sb0);
            hw[0] = make_float4(hv[0], hv[1], hv[2], hv[3]);
            hw[1] = make_float4(hv[4], hv[5], hv[6], hv[7]);
        }
        // next iteration's barrier (A) orders these writes before the next gemm
    }

    // ---- epilogue: temporal mean + BatchNorm (eval mode) ----
    float scale = bn_gamma[u] * rsqrtf(bn_var[u] + 1e-5f);
    float shift = bn_beta[u] - bn_mean[u] * scale;
    const float inv = 1.0f / (float)T_LEN;
    size_t ob = ((size_t)path * B_TOT + bbase + sb0) * UDIM + u;
#pragma unroll
    for (int j = 0; j < 8; j++) {
        out[ob + (size_t)j * UDIM] = s[j] * inv * scale + shift;
    }
}

extern "C" void kernel_launch(void* const* d_in, const int* in_sizes, int n_in,
                              void* d_out, int out_size) {
    const float* x_st  = (const float*)d_in[0];
    const float* x_sc  = (const float*)d_in[1];
    const float* W_ih  = (const float*)d_in[2];
    const float* W_hh  = (const float*)d_in[3];
    const float* b_ih  = (const float*)d_in[4];
    const float* b_hh  = (const float*)d_in[5];
    const float* gamma = (const float*)d_in[6];
    const float* beta  = (const float*)d_in[7];
    const float* mean  = (const float*)d_in[8];
    const float* var   = (const float*)d_in[9];

    // raise dynamic smem limit (idempotent; not a stream op, graph-capture safe)
    cudaFuncSetAttribute(lstm_kernel, cudaFuncAttributeMaxDynamicSharedMemorySize,
                         SMEM_TOTAL_BYTES);

    prep_kernel<<<KTOT, NG>>>(W_ih, W_hh, b_ih, b_hh);

    dim3 grid(B_TOT / BT, 2);   // (128, 2)
    lstm_kernel<<<grid, NTH, SMEM_TOTAL_BYTES>>>(x_st, x_sc, gamma, beta, mean, var,
                                                 (float*)d_out);
}